// round 1
// baseline (speedup 1.0000x reference)
#include <cuda_runtime.h>
#include <math.h>

#define B_  256
#define T_  100
#define F_  1024
#define H1_ 512
#define H2_ 512
#define O_  10

// ---------------- device scratch (no allocations allowed) ----------------
__device__ float d_Wq1[H1_ * F_];
__device__ float d_Wq2[H2_ * H1_];
__device__ float d_Wqi[H2_ * H2_];
__device__ float d_Wqo[H2_ * H2_];
__device__ float d_Wq3[O_ * H2_];
__device__ float d_cur1[(size_t)T_ * B_ * H1_];   // [b*T+t, h1]
__device__ float d_m1[B_ * H1_];
__device__ float d_s1[B_ * H1_];
__device__ float d_bmem[B_ * H2_];
__device__ float d_bs[B_ * H2_];
__device__ float d_rmem[B_ * H2_];
__device__ float d_rspk[B_ * H2_];
__device__ float d_m2[B_ * O_];
__device__ float d_scales[5];   // max|W| per matrix (as float bits, atomicMax-int)

// ---------------- init ----------------
__global__ void init_kernel() {
    int i = blockIdx.x * blockDim.x + threadIdx.x;
    if (i < B_ * H2_) {
        d_m1[i] = 0.f; d_bmem[i] = 0.f; d_rmem[i] = 0.f; d_rspk[i] = 0.f;
    }
    if (i < B_ * O_) d_m2[i] = 0.f;
    if (i < 5) d_scales[i] = 0.f;
}

// ---------------- max|w| reduction (positive floats compare as ints) ----------------
__global__ void maxabs_kernel(const float* __restrict__ w, int n, int slot) {
    __shared__ float red[256];
    float m = 0.f;
    for (int i = blockIdx.x * blockDim.x + threadIdx.x; i < n; i += gridDim.x * blockDim.x)
        m = fmaxf(m, fabsf(w[i]));
    red[threadIdx.x] = m;
    __syncthreads();
    for (int s = 128; s > 0; s >>= 1) {
        if (threadIdx.x < s) red[threadIdx.x] = fmaxf(red[threadIdx.x], red[threadIdx.x + s]);
        __syncthreads();
    }
    if (threadIdx.x == 0) atomicMax((int*)&d_scales[slot], __float_as_int(red[0]));
}

// ---------------- fake quant (matches jnp ops: /, round-half-even, clip, *) ----------------
__device__ __forceinline__ float fq(float w, float mx) {
    float scale = mx / 127.0f;
    float r = rintf(w / scale);                 // RNE == jnp.round
    r = fminf(fmaxf(r, -128.f), 127.f);
    return r * scale;
}

__global__ void quant_kernel(const float* __restrict__ W1, const float* __restrict__ W2,
                             const float* __restrict__ Wi, const float* __restrict__ Wo,
                             const float* __restrict__ W3) {
    int i = blockIdx.x * blockDim.x + threadIdx.x;
    const int n1 = H1_ * F_;       // 524288
    const int n2 = H2_ * H1_;      // 262144
    const int n3 = O_ * H2_;       // 5120
    if (i < n1) { d_Wq1[i] = fq(W1[i], d_scales[0]); return; }
    i -= n1;
    if (i < n2) { d_Wq2[i] = fq(W2[i], d_scales[1]); return; }
    i -= n2;
    if (i < n2) { d_Wqi[i] = fq(Wi[i], d_scales[2]); return; }
    i -= n2;
    if (i < n2) { d_Wqo[i] = fq(Wo[i], d_scales[3]); return; }
    i -= n2;
    if (i < n3) { d_Wq3[i] = fq(W3[i], d_scales[4]); return; }
}

// ---------------- big first-layer GEMM: cur1[r,h] = dot(data[r,:], Wq1[h,:]) ----------------
// A: [25600, 1024] row-major (r = b*T + t), W: [512, 1024] row-major. 64x64 tile, BK=16.
__global__ void __launch_bounds__(256) gemm_cur1(const float* __restrict__ A) {
    __shared__ float As[16][64];
    __shared__ float Bs[16][64];
    int tid = threadIdx.x;
    int m0 = blockIdx.y * 64, n0 = blockIdx.x * 64;
    int lr = tid >> 2;          // 0..63
    int lk = (tid & 3) * 4;     // 0,4,8,12
    int ty = tid >> 4, tx = tid & 15;
    const float* Ap = A + (size_t)(m0 + lr) * F_ + lk;
    const float* Wp = d_Wq1 + (size_t)(n0 + lr) * F_ + lk;
    float acc[4][4] = {};
    for (int k0 = 0; k0 < F_; k0 += 16) {
        float4 av = *(const float4*)(Ap + k0);
        float4 bv = *(const float4*)(Wp + k0);
        __syncthreads();
        As[lk + 0][lr] = av.x; As[lk + 1][lr] = av.y; As[lk + 2][lr] = av.z; As[lk + 3][lr] = av.w;
        Bs[lk + 0][lr] = bv.x; Bs[lk + 1][lr] = bv.y; Bs[lk + 2][lr] = bv.z; Bs[lk + 3][lr] = bv.w;
        __syncthreads();
#pragma unroll
        for (int kk = 0; kk < 16; kk++) {
            float4 a = *(const float4*)&As[kk][ty * 4];
            float4 b = *(const float4*)&Bs[kk][tx * 4];
            acc[0][0] += a.x * b.x; acc[0][1] += a.x * b.y; acc[0][2] += a.x * b.z; acc[0][3] += a.x * b.w;
            acc[1][0] += a.y * b.x; acc[1][1] += a.y * b.y; acc[1][2] += a.y * b.z; acc[1][3] += a.y * b.w;
            acc[2][0] += a.z * b.x; acc[2][1] += a.z * b.y; acc[2][2] += a.z * b.z; acc[2][3] += a.z * b.w;
            acc[3][0] += a.w * b.x; acc[3][1] += a.w * b.y; acc[3][2] += a.w * b.z; acc[3][3] += a.w * b.w;
        }
    }
#pragma unroll
    for (int i = 0; i < 4; i++)
#pragma unroll
        for (int j = 0; j < 4; j++)
            d_cur1[(size_t)(m0 + ty * 4 + i) * H1_ + (n0 + tx * 4 + j)] = acc[i][j];
}

// ---------------- step A: bmem/bs GEMM (rspk_prev @ Wqi.T) + elementwise m1/s1 ----------------
// 32x32 tile over [B=256, H2=512], grid (16, 8), 256 threads, 2x2 per thread.
__global__ void __launch_bounds__(256) stepA_kernel(int t,
        const float* __restrict__ beta_in, const float* __restrict__ beta_back,
        const float* __restrict__ vth_in, const float* __restrict__ vth_back) {
    __shared__ float As[32][33];
    __shared__ float Bs[32][33];
    int tid = threadIdx.x;
    int m0 = blockIdx.y * 32;   // batch
    int n0 = blockIdx.x * 32;   // h
    int lr = tid >> 3;          // 0..31
    int lk = (tid & 7) * 4;     // 0..28
    int ty = tid >> 4, tx = tid & 15;
    const float* Ap = d_rspk + (m0 + lr) * H2_ + lk;
    const float* Wp = d_Wqi  + (n0 + lr) * H2_ + lk;
    float acc[2][2] = {};
    for (int k0 = 0; k0 < H2_; k0 += 32) {
        float4 av = *(const float4*)(Ap + k0);
        float4 bv = *(const float4*)(Wp + k0);
        __syncthreads();
        As[lk + 0][lr] = av.x; As[lk + 1][lr] = av.y; As[lk + 2][lr] = av.z; As[lk + 3][lr] = av.w;
        Bs[lk + 0][lr] = bv.x; Bs[lk + 1][lr] = bv.y; Bs[lk + 2][lr] = bv.z; Bs[lk + 3][lr] = bv.w;
        __syncthreads();
#pragma unroll
        for (int kk = 0; kk < 32; kk++) {
            float a0 = As[kk][ty * 2], a1 = As[kk][ty * 2 + 1];
            float b0 = Bs[kk][tx * 2], b1 = Bs[kk][tx * 2 + 1];
            acc[0][0] += a0 * b0; acc[0][1] += a0 * b1;
            acc[1][0] += a1 * b0; acc[1][1] += a1 * b1;
        }
    }
    float bb  = fminf(fmaxf(*beta_back, 0.f), 1.f);
    float b1c = fminf(fmaxf(*beta_in,   0.f), 1.f);
    float vb = *vth_back, vi = *vth_in;
#pragma unroll
    for (int i = 0; i < 2; i++)
#pragma unroll
        for (int j = 0; j < 2; j++) {
            int b = m0 + ty * 2 + i, h = n0 + tx * 2 + j;
            int idx = b * H2_ + h;
            float bm = bb * d_bmem[idx] + acc[i][j];
            float sp = bm > vb ? 1.f : 0.f;
            d_bmem[idx] = bm * (1.f - sp);
            d_bs[idx] = sp;
            // elementwise leaky1 (H1_ == H2_, same index space)
            float m = b1c * d_m1[idx] + d_cur1[((size_t)b * T_ + t) * H1_ + h];
            float s = m > vi ? 1.f : 0.f;
            d_m1[idx] = m * (1.f - s);
            d_s1[idx] = s;
        }
}

// ---------------- step B: rmem = br*rmem + s1@Wq2.T + bs@Wqo.T ; rspk ----------------
__global__ void __launch_bounds__(256) stepB_kernel(
        const float* __restrict__ beta_rec, const float* __restrict__ vth_rec) {
    __shared__ float As[32][33];
    __shared__ float Bs[32][33];
    int tid = threadIdx.x;
    int m0 = blockIdx.y * 32;
    int n0 = blockIdx.x * 32;
    int lr = tid >> 3;
    int lk = (tid & 7) * 4;
    int ty = tid >> 4, tx = tid & 15;
    float acc[2][2] = {};
#pragma unroll
    for (int seg = 0; seg < 2; seg++) {
        const float* Ap = (seg == 0 ? d_s1 : d_bs) + (m0 + lr) * H2_ + lk;
        const float* Wp = (seg == 0 ? d_Wq2 : d_Wqo) + (n0 + lr) * H2_ + lk;
        for (int k0 = 0; k0 < H2_; k0 += 32) {
            float4 av = *(const float4*)(Ap + k0);
            float4 bv = *(const float4*)(Wp + k0);
            __syncthreads();
            As[lk + 0][lr] = av.x; As[lk + 1][lr] = av.y; As[lk + 2][lr] = av.z; As[lk + 3][lr] = av.w;
            Bs[lk + 0][lr] = bv.x; Bs[lk + 1][lr] = bv.y; Bs[lk + 2][lr] = bv.z; Bs[lk + 3][lr] = bv.w;
            __syncthreads();
#pragma unroll
            for (int kk = 0; kk < 32; kk++) {
                float a0 = As[kk][ty * 2], a1 = As[kk][ty * 2 + 1];
                float b0 = Bs[kk][tx * 2], b1 = Bs[kk][tx * 2 + 1];
                acc[0][0] += a0 * b0; acc[0][1] += a0 * b1;
                acc[1][0] += a1 * b0; acc[1][1] += a1 * b1;
            }
        }
    }
    float br = fminf(fmaxf(*beta_rec, 0.f), 1.f);
    float vr = *vth_rec;
#pragma unroll
    for (int i = 0; i < 2; i++)
#pragma unroll
        for (int j = 0; j < 2; j++) {
            int idx = (m0 + ty * 2 + i) * H2_ + (n0 + tx * 2 + j);
            float rm = br * d_rmem[idx] + acc[i][j];
            float sp = rm > vr ? 1.f : 0.f;
            d_rmem[idx] = rm * (1.f - sp);
            d_rspk[idx] = sp;
        }
}

// ---------------- step C: m2 = bo*m2 + rspk@Wq3.T ; write output spikes ----------------
__global__ void __launch_bounds__(128) stepC_kernel(int t, float* __restrict__ out,
        const float* __restrict__ beta_out, const float* __restrict__ vth_out) {
    __shared__ float spk[H2_];
    int b = blockIdx.x;
    int tid = threadIdx.x;
    for (int k = tid; k < H2_; k += 128) spk[k] = d_rspk[b * H2_ + k];
    __syncthreads();
    int warp = tid >> 5, lane = tid & 31;
    float bo = fminf(fmaxf(*beta_out, 0.f), 1.f);
    float vo = *vth_out;
    for (int o = warp; o < O_; o += 4) {
        float s = 0.f;
        const float* wrow = d_Wq3 + o * H2_;
#pragma unroll
        for (int k = lane; k < H2_; k += 32) s += spk[k] * wrow[k];
#pragma unroll
        for (int off = 16; off; off >>= 1) s += __shfl_down_sync(0xffffffffu, s, off);
        if (lane == 0) {
            float m = bo * d_m2[b * O_ + o] + s;
            float sp = m > vo ? 1.f : 0.f;
            d_m2[b * O_ + o] = m * (1.f - sp);
            out[((size_t)t * B_ + b) * O_ + o] = sp;
        }
    }
}

// ---------------- launch ----------------
extern "C" void kernel_launch(void* const* d_in, const int* in_sizes, int n_in,
                              void* d_out, int out_size) {
    const float* data = (const float*)d_in[0];
    const float* W1   = (const float*)d_in[1];
    const float* W2   = (const float*)d_in[2];
    const float* Win  = (const float*)d_in[3];
    const float* Wout = (const float*)d_in[4];
    const float* W3   = (const float*)d_in[5];
    const float* beta_in   = (const float*)d_in[6];
    const float* beta_rec  = (const float*)d_in[7];
    const float* beta_back = (const float*)d_in[8];
    const float* beta_out  = (const float*)d_in[9];
    const float* vth_in    = (const float*)d_in[10];
    const float* vth_rec   = (const float*)d_in[11];
    const float* vth_back  = (const float*)d_in[12];
    const float* vth_out   = (const float*)d_in[13];
    float* out = (float*)d_out;

    init_kernel<<<(B_ * H2_ + 255) / 256, 256>>>();

    maxabs_kernel<<<128, 256>>>(W1,   H1_ * F_,  0);
    maxabs_kernel<<<128, 256>>>(W2,   H2_ * H1_, 1);
    maxabs_kernel<<<128, 256>>>(Win,  H2_ * H2_, 2);
    maxabs_kernel<<<128, 256>>>(Wout, H2_ * H2_, 3);
    maxabs_kernel<<<32,  256>>>(W3,   O_ * H2_,  4);

    int n_tot = H1_ * F_ + 3 * (H2_ * H1_) + O_ * H2_;
    quant_kernel<<<(n_tot + 255) / 256, 256>>>(W1, W2, Win, Wout, W3);

    // big first-layer GEMM for all timesteps
    gemm_cur1<<<dim3(H1_ / 64, (B_ * T_) / 64), 256>>>(data);

    dim3 gstep(H2_ / 32, B_ / 32);   // (16, 8) = 128 blocks
    for (int t = 0; t < T_; t++) {
        stepA_kernel<<<gstep, 256>>>(t, beta_in, beta_back, vth_in, vth_back);
        stepB_kernel<<<gstep, 256>>>(beta_rec, vth_rec);
        stepC_kernel<<<B_, 128>>>(t, out, beta_out, vth_out);
    }
}

// round 2
// speedup vs baseline: 2.7099x; 2.7099x over previous
#include <cuda_runtime.h>
#include <math.h>

#define B_  256
#define T_  100
#define F_  1024
#define H1_ 512
#define H2_ 512
#define O_  10
#define KW  128          // u32 words per 512-int8 row
#define NB  128          // persistent blocks (16 h-tiles x 8 b-tiles)

// ---------------- device scratch ----------------
__device__ float d_Wq1[H1_ * F_];                 // dequantized fp32 W1
__device__ unsigned d_W2P[H2_ * KW];              // packed int8 q
__device__ unsigned d_WiP[H2_ * KW];
__device__ unsigned d_WoP[H2_ * KW];
__device__ unsigned d_W3P[O_ * KW];
__device__ float d_cur1[(size_t)T_ * B_ * H1_];   // [b*T+t, h1]
__device__ float d_m1[B_ * H1_];
__device__ float d_bmem[B_ * H2_];
__device__ float d_rmem[B_ * H2_];
__device__ float d_m2[B_ * O_];
__device__ unsigned d_s1P[B_ * KW];               // spikes packed as bytes
__device__ unsigned d_bsP[B_ * KW];
__device__ unsigned d_rspkP[B_ * KW];
__device__ float d_scales[5];
__device__ unsigned d_barCnt;
__device__ unsigned d_barGen;

// ---------------- init ----------------
__global__ void init_kernel() {
    int i = blockIdx.x * blockDim.x + threadIdx.x;
    if (i < B_ * H2_) { d_m1[i] = 0.f; d_bmem[i] = 0.f; d_rmem[i] = 0.f; }
    if (i < B_ * O_) d_m2[i] = 0.f;
    if (i < B_ * KW) d_rspkP[i] = 0u;
    if (i == 0) { d_barCnt = 0u; d_barGen = 0u; }
    if (i < 5) d_scales[i] = 0.f;
}

// ---------------- max|w| (nonneg float compares as int) ----------------
__global__ void maxabs_kernel(const float* __restrict__ w, int n, int slot) {
    __shared__ float red[256];
    float m = 0.f;
    for (int i = blockIdx.x * blockDim.x + threadIdx.x; i < n; i += gridDim.x * blockDim.x)
        m = fmaxf(m, fabsf(w[i]));
    red[threadIdx.x] = m;
    __syncthreads();
    for (int s = 128; s > 0; s >>= 1) {
        if (threadIdx.x < s) red[threadIdx.x] = fmaxf(red[threadIdx.x], red[threadIdx.x + s]);
        __syncthreads();
    }
    if (threadIdx.x == 0) atomicMax((int*)&d_scales[slot], __float_as_int(red[0]));
}

// fake-quant integer level (matches jnp: /, round-half-even, clip)
__device__ __forceinline__ int qlev(float w, float scale) {
    float r = rintf(w / scale);
    r = fminf(fmaxf(r, -128.f), 127.f);
    return (int)r;
}

// W1 -> dequantized fp32
__global__ void quant_w1(const float* __restrict__ W1) {
    int i = blockIdx.x * blockDim.x + threadIdx.x;
    if (i >= H1_ * F_) return;
    float scale = d_scales[0] / 127.0f;
    d_Wq1[i] = (float)qlev(W1[i], scale) * scale;
}

// W2/Win/Wout/W3 -> packed int8 words
__global__ void pack_kernel(const float* __restrict__ W2, const float* __restrict__ Wi,
                            const float* __restrict__ Wo, const float* __restrict__ W3) {
    int i = blockIdx.x * blockDim.x + threadIdx.x;
    const int NW = H2_ * KW;                  // 65536 words per 512x512 matrix
    const float* src; unsigned* dst; float mx; int local;
    if (i < NW)            { src = W2; dst = d_W2P; mx = d_scales[1]; local = i; }
    else if (i < 2 * NW)   { src = Wi; dst = d_WiP; mx = d_scales[2]; local = i - NW; }
    else if (i < 3 * NW)   { src = Wo; dst = d_WoP; mx = d_scales[3]; local = i - 2 * NW; }
    else if (i < 3 * NW + O_ * KW) { src = W3; dst = d_W3P; mx = d_scales[4]; local = i - 3 * NW; }
    else return;
    float scale = mx / 127.0f;
    float4 w = *(const float4*)(src + (size_t)local * 4);
    int q0 = qlev(w.x, scale), q1 = qlev(w.y, scale), q2 = qlev(w.z, scale), q3 = qlev(w.w, scale);
    dst[local] = (unsigned)(q0 & 0xFF) | ((unsigned)(q1 & 0xFF) << 8) |
                 ((unsigned)(q2 & 0xFF) << 16) | ((unsigned)(q3 & 0xFF) << 24);
}

// ---------------- first-layer GEMM: cur1 = data @ Wq1.T ----------------
// tile 128(M) x 64(N), 256 threads, 8x4 per thread, BK=16
__global__ void __launch_bounds__(256) gemm_cur1(const float* __restrict__ A) {
    __shared__ float As[16][132];
    __shared__ float Bs[16][68];
    int tid = threadIdx.x;
    int m0 = blockIdx.y * 128, n0 = blockIdx.x * 64;
    int ty = tid >> 4, tx = tid & 15;
    int lr = tid >> 2;            // 0..63
    int lk = (tid & 3) * 4;       // 0,4,8,12
    const float* Ap0 = A + (size_t)(m0 + lr) * F_ + lk;
    const float* Ap1 = A + (size_t)(m0 + 64 + lr) * F_ + lk;
    const float* Wp  = d_Wq1 + (size_t)(n0 + lr) * F_ + lk;
    float acc[8][4] = {};
    for (int k0 = 0; k0 < F_; k0 += 16) {
        float4 a0 = *(const float4*)(Ap0 + k0);
        float4 a1 = *(const float4*)(Ap1 + k0);
        float4 bv = *(const float4*)(Wp + k0);
        __syncthreads();
        As[lk + 0][lr] = a0.x; As[lk + 1][lr] = a0.y; As[lk + 2][lr] = a0.z; As[lk + 3][lr] = a0.w;
        As[lk + 0][64 + lr] = a1.x; As[lk + 1][64 + lr] = a1.y; As[lk + 2][64 + lr] = a1.z; As[lk + 3][64 + lr] = a1.w;
        Bs[lk + 0][lr] = bv.x; Bs[lk + 1][lr] = bv.y; Bs[lk + 2][lr] = bv.z; Bs[lk + 3][lr] = bv.w;
        __syncthreads();
#pragma unroll
        for (int kk = 0; kk < 16; kk++) {
            float4 b4 = *(const float4*)&Bs[kk][tx * 4];
            float4 x0 = *(const float4*)&As[kk][ty * 8];
            float4 x1 = *(const float4*)&As[kk][ty * 8 + 4];
            float am[8] = {x0.x, x0.y, x0.z, x0.w, x1.x, x1.y, x1.z, x1.w};
            float bn[4] = {b4.x, b4.y, b4.z, b4.w};
#pragma unroll
            for (int i = 0; i < 8; i++)
#pragma unroll
                for (int j = 0; j < 4; j++)
                    acc[i][j] += am[i] * bn[j];
        }
    }
#pragma unroll
    for (int i = 0; i < 8; i++)
#pragma unroll
        for (int j = 0; j < 4; j++)
            d_cur1[(size_t)(m0 + ty * 8 + i) * H1_ + (n0 + tx * 4 + j)] = acc[i][j];
}

// ---------------- grid barrier (all NB blocks co-resident) ----------------
__device__ __forceinline__ void gridbar() {
    __syncthreads();
    if (threadIdx.x == 0) {
        volatile unsigned* vg = &d_barGen;
        unsigned gen = *vg;
        __threadfence();
        unsigned arr = atomicAdd(&d_barCnt, 1u);
        if (arr == NB - 1) {
            d_barCnt = 0u;
            __threadfence();
            *vg = gen + 1u;
        } else {
            while (*vg == gen) { __nanosleep(32); }
        }
    }
    __syncthreads();
}

// ---------------- persistent recurrent loop ----------------
__global__ void __launch_bounds__(256, 1) loop_kernel(float* __restrict__ out,
        const float* __restrict__ p_b1, const float* __restrict__ p_br,
        const float* __restrict__ p_bb, const float* __restrict__ p_bo,
        const float* __restrict__ p_vi, const float* __restrict__ p_vr,
        const float* __restrict__ p_vb, const float* __restrict__ p_vo) {
    __shared__ unsigned w_s[32 * 129];
    __shared__ unsigned s_s[32 * 129];

    const int tid = threadIdx.x;
    const int bx = blockIdx.x;        // 0..15 h-tile
    const int by = blockIdx.y;        // 0..7  b-tile
    const int bid = by * 16 + bx;
    const int txh = tid & 15, tyb = tid >> 4;
    const int h0 = bx * 32 + txh * 2;
    const int b0 = by * 32 + tyb * 2;
    const int wid = tid >> 5, lane = tid & 31;

    const float b1 = fminf(fmaxf(*p_b1, 0.f), 1.f);
    const float br = fminf(fmaxf(*p_br, 0.f), 1.f);
    const float bb = fminf(fmaxf(*p_bb, 0.f), 1.f);
    const float bo = fminf(fmaxf(*p_bo, 0.f), 1.f);
    const float vi = *p_vi, vr = *p_vr, vb = *p_vb, vo = *p_vo;
    const float s2f = d_scales[1] / 127.f;
    const float sif = d_scales[2] / 127.f;
    const float sof = d_scales[3] / 127.f;
    const float s3f = d_scales[4] / 127.f;

    unsigned char* s1B = (unsigned char*)d_s1P;
    unsigned char* bsB = (unsigned char*)d_bsP;
    unsigned char* rsB = (unsigned char*)d_rspkP;

    for (int t = 0; t < T_; t++) {
        // -------- phase A --------
        // output GEMV for t-1 (uses rspk_{t-1}); this block owns batches 2*bid, 2*bid+1
        if (t > 0) {
#pragma unroll
            for (int p = wid; p < 20; p += 8) {
                int b = bid * 2 + p / 10;
                int o = p % 10;
                const int* sp = (const int*)(d_rspkP + b * KW);
                const int* wp = (const int*)(d_W3P + o * KW);
                int acc = 0;
#pragma unroll
                for (int i = 0; i < 4; i++)
                    acc = __dp4a(sp[lane * 4 + i], wp[lane * 4 + i], acc);
#pragma unroll
                for (int off = 16; off; off >>= 1) acc += __shfl_xor_sync(0xffffffffu, acc, off);
                if (lane == 0) {
                    float m = bo * d_m2[b * O_ + o] + s3f * (float)acc;
                    int sp2 = m > vo;
                    d_m2[b * O_ + o] = sp2 ? 0.f : m;
                    out[((size_t)(t - 1) * B_ + b) * O_ + o] = sp2 ? 1.f : 0.f;
                }
            }
        }
        // GEMM: bs-drive = rspk_{t-1} @ Wqi.T for tile (32b x 32h)
        {
            const unsigned* wg = d_WiP + bx * 32 * KW;
            const unsigned* sg = d_rspkP + by * 32 * KW;
            for (int i = tid; i < 32 * KW; i += 256) {
                int r = i >> 7, c = i & 127;
                w_s[r * 129 + c] = wg[i];
                s_s[r * 129 + c] = sg[i];
            }
            __syncthreads();
            int a00 = 0, a01 = 0, a10 = 0, a11 = 0;
            const unsigned* wr0 = w_s + (txh * 2) * 129;
            const unsigned* wr1 = wr0 + 129;
            const unsigned* sr0 = s_s + (tyb * 2) * 129;
            const unsigned* sr1 = sr0 + 129;
#pragma unroll 8
            for (int kw = 0; kw < KW; kw++) {
                int w0 = (int)wr0[kw], w1 = (int)wr1[kw];
                int x0 = (int)sr0[kw], x1 = (int)sr1[kw];
                a00 = __dp4a(x0, w0, a00); a01 = __dp4a(x0, w1, a01);
                a10 = __dp4a(x1, w0, a10); a11 = __dp4a(x1, w1, a11);
            }
            int accs[2][2] = {{a00, a01}, {a10, a11}};
#pragma unroll
            for (int bi = 0; bi < 2; bi++)
#pragma unroll
                for (int hi = 0; hi < 2; hi++) {
                    int b = b0 + bi, h = h0 + hi;
                    int idx = b * H2_ + h;
                    float bm = bb * d_bmem[idx] + sif * (float)accs[bi][hi];
                    int bsp = bm > vb;
                    d_bmem[idx] = bsp ? 0.f : bm;
                    bsB[idx] = (unsigned char)bsp;
                    float mm = b1 * d_m1[idx] + d_cur1[((size_t)b * T_ + t) * H1_ + h];
                    int s1i = mm > vi;
                    d_m1[idx] = s1i ? 0.f : mm;
                    s1B[idx] = (unsigned char)s1i;
                }
        }
        gridbar();

        // -------- phase B: rmem = br*rmem + s1@Wq2.T + bs@Wqo.T --------
        {
            float cur[2][2] = {};
#pragma unroll
            for (int seg = 0; seg < 2; seg++) {
                const unsigned* wg = (seg == 0 ? d_W2P : d_WoP) + bx * 32 * KW;
                const unsigned* sg = (seg == 0 ? d_s1P : d_bsP) + by * 32 * KW;
                __syncthreads();
                for (int i = tid; i < 32 * KW; i += 256) {
                    int r = i >> 7, c = i & 127;
                    w_s[r * 129 + c] = wg[i];
                    s_s[r * 129 + c] = sg[i];
                }
                __syncthreads();
                int a00 = 0, a01 = 0, a10 = 0, a11 = 0;
                const unsigned* wr0 = w_s + (txh * 2) * 129;
                const unsigned* wr1 = wr0 + 129;
                const unsigned* sr0 = s_s + (tyb * 2) * 129;
                const unsigned* sr1 = sr0 + 129;
#pragma unroll 8
                for (int kw = 0; kw < KW; kw++) {
                    int w0 = (int)wr0[kw], w1 = (int)wr1[kw];
                    int x0 = (int)sr0[kw], x1 = (int)sr1[kw];
                    a00 = __dp4a(x0, w0, a00); a01 = __dp4a(x0, w1, a01);
                    a10 = __dp4a(x1, w0, a10); a11 = __dp4a(x1, w1, a11);
                }
                float sc = seg == 0 ? s2f : sof;
                cur[0][0] += sc * (float)a00; cur[0][1] += sc * (float)a01;
                cur[1][0] += sc * (float)a10; cur[1][1] += sc * (float)a11;
            }
#pragma unroll
            for (int bi = 0; bi < 2; bi++)
#pragma unroll
                for (int hi = 0; hi < 2; hi++) {
                    int b = b0 + bi, h = h0 + hi;
                    int idx = b * H2_ + h;
                    float rm = br * d_rmem[idx] + cur[bi][hi];
                    int rsp = rm > vr;
                    d_rmem[idx] = rsp ? 0.f : rm;
                    rsB[idx] = (unsigned char)rsp;
                }
        }
        gridbar();
    }

    // -------- final output for t = T-1 --------
#pragma unroll
    for (int p = wid; p < 20; p += 8) {
        int b = bid * 2 + p / 10;
        int o = p % 10;
        const int* sp = (const int*)(d_rspkP + b * KW);
        const int* wp = (const int*)(d_W3P + o * KW);
        int acc = 0;
#pragma unroll
        for (int i = 0; i < 4; i++)
            acc = __dp4a(sp[lane * 4 + i], wp[lane * 4 + i], acc);
#pragma unroll
        for (int off = 16; off; off >>= 1) acc += __shfl_xor_sync(0xffffffffu, acc, off);
        if (lane == 0) {
            float m = bo * d_m2[b * O_ + o] + s3f * (float)acc;
            int sp2 = m > vo;
            d_m2[b * O_ + o] = sp2 ? 0.f : m;
            out[((size_t)(T_ - 1) * B_ + b) * O_ + o] = sp2 ? 1.f : 0.f;
        }
    }
}

// ---------------- launch ----------------
extern "C" void kernel_launch(void* const* d_in, const int* in_sizes, int n_in,
                              void* d_out, int out_size) {
    const float* data = (const float*)d_in[0];
    const float* W1   = (const float*)d_in[1];
    const float* W2   = (const float*)d_in[2];
    const float* Win  = (const float*)d_in[3];
    const float* Wout = (const float*)d_in[4];
    const float* W3   = (const float*)d_in[5];
    const float* beta_in   = (const float*)d_in[6];
    const float* beta_rec  = (const float*)d_in[7];
    const float* beta_back = (const float*)d_in[8];
    const float* beta_out  = (const float*)d_in[9];
    const float* vth_in    = (const float*)d_in[10];
    const float* vth_rec   = (const float*)d_in[11];
    const float* vth_back  = (const float*)d_in[12];
    const float* vth_out   = (const float*)d_in[13];
    float* out = (float*)d_out;

    init_kernel<<<(B_ * H2_ + 255) / 256, 256>>>();

    maxabs_kernel<<<128, 256>>>(W1,   H1_ * F_,  0);
    maxabs_kernel<<<128, 256>>>(W2,   H2_ * H1_, 1);
    maxabs_kernel<<<128, 256>>>(Win,  H2_ * H2_, 2);
    maxabs_kernel<<<128, 256>>>(Wout, H2_ * H2_, 3);
    maxabs_kernel<<<32,  256>>>(W3,   O_ * H2_,  4);

    quant_w1<<<(H1_ * F_ + 255) / 256, 256>>>(W1);
    int nwords = 3 * H2_ * KW + O_ * KW;
    pack_kernel<<<(nwords + 255) / 256, 256>>>(W2, Win, Wout, W3);

    gemm_cur1<<<dim3(H1_ / 64, (B_ * T_) / 128), 256>>>(data);

    loop_kernel<<<dim3(16, 8), 256>>>(out, beta_in, beta_rec, beta_back, beta_out,
                                      vth_in, vth_rec, vth_back, vth_out);
}